// round 14
// baseline (speedup 1.0000x reference)
#include <cuda_runtime.h>
#include <cuda_bf16.h>
#include <cstddef>
#include <cstdint>

// Problem constants
#define BB 512
#define TT 256
#define DD 128
#define HH 128
#define SS 32
#define BT (BB*TT)   // 131072

typedef unsigned long long u64;
typedef uint32_t u32;

// ---------------------------------------------------------------------------
// f32x2 packed-math helpers
// ---------------------------------------------------------------------------
__device__ __forceinline__ u64 ffma2(u64 a, u64 b, u64 c) {
    u64 d;
    asm("fma.rn.f32x2 %0, %1, %2, %3;" : "=l"(d) : "l"(a), "l"(b), "l"(c));
    return d;
}
__device__ __forceinline__ u64 add2(u64 a, u64 b) {
    u64 d;
    asm("add.rn.f32x2 %0, %1, %2;" : "=l"(d) : "l"(a), "l"(b));
    return d;
}
__device__ __forceinline__ u64 pack2(float v) {
    u64 d;
    asm("mov.b64 %0, {%1, %1};" : "=l"(d) : "f"(v));
    return d;
}
__device__ __forceinline__ u64 packab(float a, float b) {
    u64 d;
    asm("mov.b64 %0, {%1, %2};" : "=l"(d) : "f"(a), "f"(b));
    return d;
}
__device__ __forceinline__ float2 unpk(u64 x) {
    float2 f;
    asm("mov.b64 {%0, %1}, %2;" : "=f"(f.x), "=f"(f.y) : "l"(x));
    return f;
}
union F4U2 { float4 f; u64 u[2]; };

// ---------------------------------------------------------------------------
// Device-global scratch
// ---------------------------------------------------------------------------
__device__ float g_Xz[(size_t)BT * HH];
__device__ float g_Xr[(size_t)BT * HH];
__device__ float g_Xh[(size_t)BT * HH];
__device__ float g_gh[(size_t)BT * HH];
__device__ __nv_bfloat16 g_Wbh[7 * 16384];
__device__ __nv_bfloat16 g_Wbl[7 * 16384];

__global__ void noop_kernel() {}

// ---------------------------------------------------------------------------
// Kernel 0: convert 7 weight matrices fp32 -> bf16 hi/lo
// ---------------------------------------------------------------------------
__global__ void convert_w(const float* __restrict__ Wz, const float* __restrict__ Vz,
                          const float* __restrict__ Wr, const float* __restrict__ Vr,
                          const float* __restrict__ Wh, const float* __restrict__ Vh,
                          const float* __restrict__ Wdgh)
{
    const float* srcs[7] = {Wz, Vz, Wr, Vr, Wh, Vh, Wdgh};
    const float* s = srcs[blockIdx.x];
    __nv_bfloat16* dh = g_Wbh + blockIdx.x * 16384;
    __nv_bfloat16* dl = g_Wbl + blockIdx.x * 16384;
    for (int idx = threadIdx.x; idx < 16384; idx += blockDim.x) {
        float v = s[idx];
        __nv_bfloat16 h = __float2bfloat16(v);
        dh[idx] = h;
        dl[idx] = __float2bfloat16(v - __bfloat162float(h));
    }
}

// ---------------------------------------------------------------------------
// Kernel 1: precompute via warp-level mma.sync (unchanged from R13)
// ---------------------------------------------------------------------------
#define PA 136
#define PANEL_B (128 * PA * 2)
#define SM_BIAS  0
#define SM_AHI   512
#define SM_ALO   (SM_AHI + PANEL_B)
#define SM_MBF   (SM_ALO + PANEL_B)
#define SM_WHI   (SM_MBF + PANEL_B)
#define SM_WLO   (SM_WHI + PANEL_B)
#define SM_TOTAL (SM_WLO + PANEL_B)

__device__ __forceinline__ void mma_bf16(float c[4], u32 a0, u32 a1, u32 a2, u32 a3,
                                         u32 b0, u32 b1) {
    asm("mma.sync.aligned.m16n8k16.row.col.f32.bf16.bf16.f32 "
        "{%0,%1,%2,%3}, {%4,%5,%6,%7}, {%8,%9}, {%0,%1,%2,%3};"
        : "+f"(c[0]), "+f"(c[1]), "+f"(c[2]), "+f"(c[3])
        : "r"(a0), "r"(a1), "r"(a2), "r"(a3), "r"(b0), "r"(b1));
}
__device__ __forceinline__ void ldsm4(u32& r0, u32& r1, u32& r2, u32& r3, u32 a) {
    asm volatile("ldmatrix.sync.aligned.m8n8.x4.shared.b16 {%0,%1,%2,%3}, [%4];"
                 : "=r"(r0), "=r"(r1), "=r"(r2), "=r"(r3) : "r"(a));
}

__device__ __forceinline__ void gpass(const __nv_bfloat16* __restrict__ A,
                                      const __nv_bfloat16* __restrict__ W,
                                      float acc[2][8][4], int row0, int col0, int lane)
{
    const int ar = lane & 15, ac = (lane >> 4) << 3;
    const int bj = ((lane >> 4) << 3) + (lane & 7);
    const int bk = ((lane >> 3) & 1) << 3;
    #pragma unroll
    for (int kt = 0; kt < 8; kt++) {
        const int k0 = kt * 16;
        u32 a[2][4];
        #pragma unroll
        for (int mt = 0; mt < 2; mt++) {
            u32 ad = (u32)__cvta_generic_to_shared(A + (row0 + mt * 16 + ar) * PA + k0 + ac);
            ldsm4(a[mt][0], a[mt][1], a[mt][2], a[mt][3], ad);
        }
        u32 b[4][4];
        #pragma unroll
        for (int np = 0; np < 4; np++) {
            u32 bd = (u32)__cvta_generic_to_shared(W + (col0 + np * 16 + bj) * PA + k0 + bk);
            ldsm4(b[np][0], b[np][1], b[np][2], b[np][3], bd);
        }
        #pragma unroll
        for (int mt = 0; mt < 2; mt++)
            #pragma unroll
            for (int nt = 0; nt < 8; nt++)
                mma_bf16(acc[mt][nt], a[mt][0], a[mt][1], a[mt][2], a[mt][3],
                         b[nt >> 1][(nt & 1) * 2], b[nt >> 1][(nt & 1) * 2 + 1]);
    }
}

__device__ __forceinline__ void gpassAA(const __nv_bfloat16* __restrict__ A0,
                                        const __nv_bfloat16* __restrict__ A1,
                                        const __nv_bfloat16* __restrict__ W,
                                        float acc[2][8][4], int row0, int col0, int lane)
{
    const int ar = lane & 15, ac = (lane >> 4) << 3;
    const int bj = ((lane >> 4) << 3) + (lane & 7);
    const int bk = ((lane >> 3) & 1) << 3;
    #pragma unroll
    for (int kt = 0; kt < 8; kt++) {
        const int k0 = kt * 16;
        u32 a0[2][4], a1[2][4];
        #pragma unroll
        for (int mt = 0; mt < 2; mt++) {
            u32 ad0 = (u32)__cvta_generic_to_shared(A0 + (row0 + mt * 16 + ar) * PA + k0 + ac);
            ldsm4(a0[mt][0], a0[mt][1], a0[mt][2], a0[mt][3], ad0);
            u32 ad1 = (u32)__cvta_generic_to_shared(A1 + (row0 + mt * 16 + ar) * PA + k0 + ac);
            ldsm4(a1[mt][0], a1[mt][1], a1[mt][2], a1[mt][3], ad1);
        }
        u32 b[4][4];
        #pragma unroll
        for (int np = 0; np < 4; np++) {
            u32 bd = (u32)__cvta_generic_to_shared(W + (col0 + np * 16 + bj) * PA + k0 + bk);
            ldsm4(b[np][0], b[np][1], b[np][2], b[np][3], bd);
        }
        #pragma unroll
        for (int mt = 0; mt < 2; mt++)
            #pragma unroll
            for (int nt = 0; nt < 8; nt++) {
                mma_bf16(acc[mt][nt], a0[mt][0], a0[mt][1], a0[mt][2], a0[mt][3],
                         b[nt >> 1][(nt & 1) * 2], b[nt >> 1][(nt & 1) * 2 + 1]);
                mma_bf16(acc[mt][nt], a1[mt][0], a1[mt][1], a1[mt][2], a1[mt][3],
                         b[nt >> 1][(nt & 1) * 2], b[nt >> 1][(nt & 1) * 2 + 1]);
            }
    }
}

__device__ __forceinline__ void gpassBB(const __nv_bfloat16* __restrict__ A,
                                        const __nv_bfloat16* __restrict__ W0,
                                        const __nv_bfloat16* __restrict__ W1,
                                        float acc[2][8][4], int row0, int col0, int lane)
{
    const int ar = lane & 15, ac = (lane >> 4) << 3;
    const int bj = ((lane >> 4) << 3) + (lane & 7);
    const int bk = ((lane >> 3) & 1) << 3;
    #pragma unroll
    for (int kt = 0; kt < 8; kt++) {
        const int k0 = kt * 16;
        u32 a[2][4];
        #pragma unroll
        for (int mt = 0; mt < 2; mt++) {
            u32 ad = (u32)__cvta_generic_to_shared(A + (row0 + mt * 16 + ar) * PA + k0 + ac);
            ldsm4(a[mt][0], a[mt][1], a[mt][2], a[mt][3], ad);
        }
        u32 b0[4][4], b1[4][4];
        #pragma unroll
        for (int np = 0; np < 4; np++) {
            u32 bd0 = (u32)__cvta_generic_to_shared(W0 + (col0 + np * 16 + bj) * PA + k0 + bk);
            ldsm4(b0[np][0], b0[np][1], b0[np][2], b0[np][3], bd0);
            u32 bd1 = (u32)__cvta_generic_to_shared(W1 + (col0 + np * 16 + bj) * PA + k0 + bk);
            ldsm4(b1[np][0], b1[np][1], b1[np][2], b1[np][3], bd1);
        }
        #pragma unroll
        for (int mt = 0; mt < 2; mt++)
            #pragma unroll
            for (int nt = 0; nt < 8; nt++) {
                mma_bf16(acc[mt][nt], a[mt][0], a[mt][1], a[mt][2], a[mt][3],
                         b0[nt >> 1][(nt & 1) * 2], b0[nt >> 1][(nt & 1) * 2 + 1]);
                mma_bf16(acc[mt][nt], a[mt][0], a[mt][1], a[mt][2], a[mt][3],
                         b1[nt >> 1][(nt & 1) * 2], b1[nt >> 1][(nt & 1) * 2 + 1]);
            }
    }
}

__device__ __forceinline__ void stage_w(char* smem, int off, const __nv_bfloat16* g) {
    const uint4* src = (const uint4*)g;
    #pragma unroll
    for (int it = 0; it < 8; it++) {
        int cc = threadIdx.x + it * 256;
        int j = cc >> 4, k8 = (cc & 15) * 8;
        *(uint4*)(smem + off + (j * PA + k8) * 2) = src[cc];
    }
}

__global__ __launch_bounds__(256, 1)
void precompute_mma(const float* __restrict__ x,     const float* __restrict__ mask,
                    const float* __restrict__ delta, const float* __restrict__ xlast,
                    const float* __restrict__ x_mean,
                    const float* __restrict__ w_dg_x, const float* __restrict__ b_dg_x,
                    const float* __restrict__ b_dg_h,
                    const float* __restrict__ b_z, const float* __restrict__ b_r,
                    const float* __restrict__ b_h)
{
    extern __shared__ char smem[];
    float* bias_s = (float*)(smem + SM_BIAS);
    __nv_bfloat16* Ahi = (__nv_bfloat16*)(smem + SM_AHI);
    __nv_bfloat16* Alo = (__nv_bfloat16*)(smem + SM_ALO);
    __nv_bfloat16* Mbf = (__nv_bfloat16*)(smem + SM_MBF);
    __nv_bfloat16* Whi = (__nv_bfloat16*)(smem + SM_WHI);
    __nv_bfloat16* Wlo = (__nv_bfloat16*)(smem + SM_WLO);

    const int tid  = threadIdx.x;
    const int lane = tid & 31;
    const int wrp  = tid >> 5;
    const int row0 = (wrp & 3) * 32;
    const int col0 = (wrp >> 2) * 64;
    const int brow = blockIdx.x * 128;
    const int b    = brow >> 8;
    const int g = lane >> 2, t = lane & 3;

    float acc[2][8][4];

    for (int idx = tid; idx < 128 * 128; idx += 256) {
        int r = idx >> 7, d = idx & 127;
        float v = delta[(size_t)(brow + r) * DD + d];
        __nv_bfloat16 hi = __float2bfloat16(v);
        Ahi[r * PA + d] = hi;
        Alo[r * PA + d] = __float2bfloat16(v - __bfloat162float(hi));
    }
    stage_w(smem, SM_WHI, g_Wbh + 6 * 16384);
    stage_w(smem, SM_WLO, g_Wbl + 6 * 16384);
    if (tid < 128) bias_s[tid] = b_dg_h[tid];
    __syncthreads();

    #pragma unroll
    for (int mt = 0; mt < 2; mt++)
        #pragma unroll
        for (int nt = 0; nt < 8; nt++)
            #pragma unroll
            for (int q = 0; q < 4; q++) acc[mt][nt][q] = 0.0f;
    gpassAA(Ahi, Alo, Whi, acc, row0, col0, lane);
    gpass(Ahi, Wlo, acc, row0, col0, lane);
    #pragma unroll
    for (int mt = 0; mt < 2; mt++)
        #pragma unroll
        for (int nt = 0; nt < 8; nt++) {
            int j0 = col0 + nt * 8 + 2 * t;
            float2 bv = *(const float2*)&bias_s[j0];
            size_t r0g = (size_t)(brow + row0 + mt * 16 + g) * HH + j0;
            size_t r8g = r0g + (size_t)8 * HH;
            *(float2*)&g_gh[r0g] = make_float2(__expf(-fmaxf(acc[mt][nt][0] + bv.x, 0.0f)),
                                               __expf(-fmaxf(acc[mt][nt][1] + bv.y, 0.0f)));
            *(float2*)&g_gh[r8g] = make_float2(__expf(-fmaxf(acc[mt][nt][2] + bv.x, 0.0f)),
                                               __expf(-fmaxf(acc[mt][nt][3] + bv.y, 0.0f)));
        }
    __syncthreads();

    for (int idx = tid; idx < 128 * 128; idx += 256) {
        int r = idx >> 7, d = idx & 127;
        size_t gg = (size_t)(brow + r) * DD + d;
        float xv = x[gg], mv = mask[gg], dl = delta[gg], xl = xlast[gg];
        float gx = __expf(-fmaxf(fmaf(w_dg_x[d], dl, b_dg_x[d]), 0.0f));
        float xm = x_mean[b * DD + d];
        float xh = mv * xv + (1.0f - mv) * (gx * xl + (1.0f - gx) * xm);
        __nv_bfloat16 hi = __float2bfloat16(xh);
        Ahi[r * PA + d] = hi;
        Alo[r * PA + d] = __float2bfloat16(xh - __bfloat162float(hi));
        Mbf[r * PA + d] = __float2bfloat16(mv);
    }
    __syncthreads();

    const int wi[3] = {0, 2, 4};
    const int vi[3] = {1, 3, 5};
    const float* biases[3] = {b_z, b_r, b_h};
    float* outs[3] = {g_Xz, g_Xr, g_Xh};

    #pragma unroll 1
    for (int gate = 0; gate < 3; gate++) {
        stage_w(smem, SM_WHI, g_Wbh + wi[gate] * 16384);
        stage_w(smem, SM_WLO, g_Wbl + wi[gate] * 16384);
        if (tid < 128) bias_s[tid] = biases[gate][tid];
        __syncthreads();

        #pragma unroll
        for (int mt = 0; mt < 2; mt++)
            #pragma unroll
            for (int nt = 0; nt < 8; nt++)
                #pragma unroll
                for (int q = 0; q < 4; q++) acc[mt][nt][q] = 0.0f;

        gpassAA(Ahi, Alo, Whi, acc, row0, col0, lane);
        gpass(Ahi, Wlo, acc, row0, col0, lane);

        __syncthreads();
        stage_w(smem, SM_WHI, g_Wbh + vi[gate] * 16384);
        stage_w(smem, SM_WLO, g_Wbl + vi[gate] * 16384);
        __syncthreads();
        gpassBB(Mbf, Whi, Wlo, acc, row0, col0, lane);

        float* obase = outs[gate];
        #pragma unroll
        for (int mt = 0; mt < 2; mt++)
            #pragma unroll
            for (int nt = 0; nt < 8; nt++) {
                int j0 = col0 + nt * 8 + 2 * t;
                float2 bv = *(const float2*)&bias_s[j0];
                size_t r0g = (size_t)(brow + row0 + mt * 16 + g) * HH + j0;
                size_t r8g = r0g + (size_t)8 * HH;
                *(float2*)&obase[r0g] = make_float2(acc[mt][nt][0] + bv.x, acc[mt][nt][1] + bv.y);
                *(float2*)&obase[r8g] = make_float2(acc[mt][nt][2] + bv.x, acc[mt][nt][3] + bv.y);
            }
        __syncthreads();
    }
}

// ---------------------------------------------------------------------------
// Kernel 2: recurrence, 4-way k split. 128 CTAs x 512 threads.
// thread = (j = tid&127, q = tid>>7). Each thread: 32 Uz + 32 Ur regs,
// loaded DIRECTLY from gmem rows (L2-shared across CTAs). q0 owns state.
// Partials combined by q0 via 3-slot smem exchange. Uh in smem (4-way split).
// ---------------------------------------------------------------------------
#define ROFS_UH2 0                          // float2[64*128] = 16384 fl
#define ROFS_HT  16384                      // float[512]
#define ROFS_RHT (ROFS_HT + 512)            // float[512]
#define ROFS_XZR (ROFS_RHT + 512)           // u64[3*128*4] = 3072 fl
#define ROFS_XH  (ROFS_XZR + 3072)          // u64[3*128*2] = 1536 fl
#define RSMEM_FL (ROFS_XH + 1536)           // 22016 fl = 88064 B

__global__ __launch_bounds__(512, 1)
void recurrent_kernel(const float* __restrict__ hs0,
                      const float* __restrict__ Uz, const float* __restrict__ Ur,
                      const float* __restrict__ Uh,
                      const float* __restrict__ statics,
                      const float* __restrict__ W_out, const float* __restrict__ b_out,
                      float* __restrict__ out)
{
    extern __shared__ float sm[];
    float2* Uh2  = (float2*)(sm + ROFS_UH2);   // [kp][j]
    float*  hT   = sm + ROFS_HT;               // [j][4 rows]
    float*  rhT  = sm + ROFS_RHT;
    u64*    xchZR = (u64*)(sm + ROFS_XZR);     // [q-1][j][4]
    u64*    xchH  = (u64*)(sm + ROFS_XH);      // [q-1][j][2]

    const int tid = threadIdx.x;
    const int j   = tid & 127;
    const int q   = tid >> 7;                  // 0..3
    const bool q0 = (q == 0);
    const int b0  = blockIdx.x * 4;

    // stage Uh (float2 per kp), coalesced-ish one-time
    for (int idx = tid; idx < 64 * 128; idx += 512) {
        int kp = idx >> 7, jj = idx & 127;
        Uh2[kp * 128 + jj] = make_float2(Uh[jj * 128 + 2 * kp],
                                         Uh[jj * 128 + 2 * kp + 1]);
    }

    // this thread's U row slices straight from gmem (rows L2-shared by all CTAs)
    float uzr_[32], urr_[32];
    {
        const float4* zr = (const float4*)(Uz + j * 128 + q * 32);
        const float4* rr = (const float4*)(Ur + j * 128 + q * 32);
        #pragma unroll
        for (int i = 0; i < 8; i++) {
            float4 a = zr[i], c = rr[i];
            uzr_[4 * i] = a.x; uzr_[4 * i + 1] = a.y; uzr_[4 * i + 2] = a.z; uzr_[4 * i + 3] = a.w;
            urr_[4 * i] = c.x; urr_[4 * i + 1] = c.y; urr_[4 * i + 2] = c.z; urr_[4 * i + 3] = c.w;
        }
    }

    float hreg[4], cG[4], cXz[4], cXr[4], cXh[4], zg[4];
    if (q0) {
        #pragma unroll
        for (int r = 0; r < 4; r++) {
            hreg[r] = hs0[(b0 + r) * HH + j];
            int g = ((b0 + r) * TT) * HH + j;
            cG[r] = g_gh[g]; cXz[r] = g_Xz[g]; cXr[r] = g_Xr[g]; cXh[r] = g_Xh[g];
        }
    }
    __syncthreads();

    u64 sh01 = 0, sh23 = 0;   // Xh seed snapshot (survives prefetch)

    #pragma unroll 1
    for (int t = 0; t < TT; t++) {
        if (q0) {
            #pragma unroll
            for (int r = 0; r < 4; r++) hreg[r] *= cG[r];
            *(float4*)&hT[j * 4] = make_float4(hreg[0], hreg[1], hreg[2], hreg[3]);
        }
        __syncthreads();   // B1: hT published

        // seed q0 accumulators with CURRENT gate inputs, snapshot Xh, then prefetch
        u64 az01, az23, ar01, ar23;
        if (q0) {
            az01 = packab(cXz[0], cXz[1]); az23 = packab(cXz[2], cXz[3]);
            ar01 = packab(cXr[0], cXr[1]); ar23 = packab(cXr[2], cXr[3]);
            sh01 = packab(cXh[0], cXh[1]); sh23 = packab(cXh[2], cXh[3]);
            if (t + 1 < TT) {
                #pragma unroll
                for (int r = 0; r < 4; r++) {
                    int g = ((b0 + r) * TT + t + 1) * HH + j;
                    cG[r] = g_gh[g]; cXz[r] = g_Xz[g];
                    cXr[r] = g_Xr[g]; cXh[r] = g_Xh[g];
                }
            }
        } else {
            az01 = 0; az23 = 0; ar01 = 0; ar23 = 0;
        }

        // ---- z+r partials over k in [32q, 32q+32), U from registers ----
        #pragma unroll
        for (int kk = 0; kk < 32; kk++) {
            F4U2 hv; hv.f = *(const float4*)&hT[(q * 32 + kk) * 4];
            u64 uz2 = pack2(uzr_[kk]);
            u64 ur2 = pack2(urr_[kk]);
            az01 = ffma2(hv.u[0], uz2, az01);
            az23 = ffma2(hv.u[1], uz2, az23);
            ar01 = ffma2(hv.u[0], ur2, ar01);
            ar23 = ffma2(hv.u[1], ur2, ar23);
        }

        if (!q0) {
            u64* dst = &xchZR[(q - 1) * 512 + 4 * j];
            dst[0] = az01; dst[1] = az23; dst[2] = ar01; dst[3] = ar23;
        }
        __syncthreads();   // B2: z/r partials exchanged

        if (q0) {
            #pragma unroll
            for (int p = 0; p < 3; p++) {
                const u64* src = &xchZR[p * 512 + 4 * j];
                az01 = add2(az01, src[0]);
                az23 = add2(az23, src[1]);
                ar01 = add2(ar01, src[2]);
                ar23 = add2(ar23, src[3]);
            }
            float2 z01 = unpk(az01), z23 = unpk(az23);
            float2 r01 = unpk(ar01), r23 = unpk(ar23);
            zg[0] = 1.0f / (1.0f + __expf(-z01.x));
            zg[1] = 1.0f / (1.0f + __expf(-z01.y));
            zg[2] = 1.0f / (1.0f + __expf(-z23.x));
            zg[3] = 1.0f / (1.0f + __expf(-z23.y));
            float rg0 = 1.0f / (1.0f + __expf(-r01.x));
            float rg1 = 1.0f / (1.0f + __expf(-r01.y));
            float rg2 = 1.0f / (1.0f + __expf(-r23.x));
            float rg3 = 1.0f / (1.0f + __expf(-r23.y));
            *(float4*)&rhT[j * 4] = make_float4(rg0 * hreg[0], rg1 * hreg[1],
                                                rg2 * hreg[2], rg3 * hreg[3]);
        }
        __syncthreads();   // B3: rhT published

        // ---- h_tilde partials over kp in [16q, 16q+16), Uh from smem ----
        u64 ah01 = q0 ? sh01 : 0ull;
        u64 ah23 = q0 ? sh23 : 0ull;
        #pragma unroll
        for (int kk = 0; kk < 16; kk++) {
            int kp = q * 16 + kk;
            int k4 = kp * 8;
            F4U2 re; re.f = *(const float4*)&rhT[k4];
            F4U2 ro; ro.f = *(const float4*)&rhT[k4 + 4];
            float2 u2 = Uh2[kp * 128 + j];
            u64 uhe = pack2(u2.x), uho = pack2(u2.y);
            ah01 = ffma2(re.u[0], uhe, ah01);
            ah23 = ffma2(re.u[1], uhe, ah23);
            ah01 = ffma2(ro.u[0], uho, ah01);
            ah23 = ffma2(ro.u[1], uho, ah23);
        }
        if (!q0) {
            u64* dst = &xchH[(q - 1) * 256 + 2 * j];
            dst[0] = ah01; dst[1] = ah23;
        }
        __syncthreads();   // B4: h_tilde partials exchanged

        if (q0) {
            #pragma unroll
            for (int p = 0; p < 3; p++) {
                const u64* src = &xchH[p * 256 + 2 * j];
                ah01 = add2(ah01, src[0]);
                ah23 = add2(ah23, src[1]);
            }
            float2 p01 = unpk(ah01), p23 = unpk(ah23);
            float pre[4] = {p01.x, p01.y, p23.x, p23.y};
            #pragma unroll
            for (int r = 0; r < 4; r++) {
                float ht = 2.0f / (1.0f + __expf(-2.0f * pre[r])) - 1.0f;
                hreg[r] = (1.0f - zg[r]) * hreg[r] + zg[r] * ht;
            }
        }
    }

    // ---- classifier ----
    __syncthreads();
    if (q0) {
        float wj = W_out[j];
        *(float4*)&hT[j * 4] = make_float4(hreg[0] * wj, hreg[1] * wj,
                                           hreg[2] * wj, hreg[3] * wj);
    }
    __syncthreads();
    for (int s = 64; s > 0; s >>= 1) {
        if (tid < s) {
            float4 a = *(const float4*)&hT[tid * 4];
            float4 c = *(const float4*)&hT[(tid + s) * 4];
            a.x += c.x; a.y += c.y; a.z += c.z; a.w += c.w;
            *(float4*)&hT[tid * 4] = a;
        }
        __syncthreads();
    }
    if (tid < 4) {
        float v = hT[tid];
        float sacc = 0.0f;
        #pragma unroll
        for (int s = 0; s < SS; s++)
            sacc = fmaf(statics[(b0 + tid) * SS + s], W_out[HH + s], sacc);
        out[b0 + tid] = v + sacc + b_out[0];
    }
}

// ---------------------------------------------------------------------------
// Launch
// ---------------------------------------------------------------------------
extern "C" void kernel_launch(void* const* d_in, const int* in_sizes, int n_in,
                              void* d_out, int out_size)
{
    const float* x       = (const float*)d_in[0];
    const float* statics = (const float*)d_in[1];
    const float* mask    = (const float*)d_in[2];
    const float* delta   = (const float*)d_in[3];
    const float* xlast   = (const float*)d_in[4];
    const float* x_mean  = (const float*)d_in[5];
    const float* hs0     = (const float*)d_in[6];
    const float* w_dg_x  = (const float*)d_in[7];
    const float* b_dg_x  = (const float*)d_in[8];
    const float* W_dg_h  = (const float*)d_in[9];
    const float* b_dg_h  = (const float*)d_in[10];
    const float* W_z = (const float*)d_in[11];
    const float* U_z = (const float*)d_in[12];
    const float* V_z = (const float*)d_in[13];
    const float* b_z = (const float*)d_in[14];
    const float* W_r = (const float*)d_in[15];
    const float* U_r = (const float*)d_in[16];
    const float* V_r = (const float*)d_in[17];
    const float* b_r = (const float*)d_in[18];
    const float* W_h = (const float*)d_in[19];
    const float* U_h = (const float*)d_in[20];
    const float* V_h = (const float*)d_in[21];
    const float* b_h = (const float*)d_in[22];
    const float* W_out = (const float*)d_in[23];
    const float* b_out = (const float*)d_in[24];
    float* out = (float*)d_out;

    const int smemB = RSMEM_FL * (int)sizeof(float);   // 88064
    cudaFuncSetAttribute(precompute_mma, cudaFuncAttributeMaxDynamicSharedMemorySize, SM_TOTAL);
    cudaFuncSetAttribute(recurrent_kernel, cudaFuncAttributeMaxDynamicSharedMemorySize, smemB);

    // one no-op: ncu capture (4th launch slot) lands on recurrent_kernel
    noop_kernel<<<1, 32>>>();
    convert_w<<<7, 256>>>(W_z, V_z, W_r, V_r, W_h, V_h, W_dg_h);
    precompute_mma<<<BT / 128, 256, SM_TOTAL>>>(x, mask, delta, xlast, x_mean,
                                                w_dg_x, b_dg_x, b_dg_h, b_z, b_r, b_h);
    recurrent_kernel<<<BB / 4, 512, smemB>>>(hs0, U_z, U_r, U_h,
                                             statics, W_out, b_out, out);
}